// round 15
// baseline (speedup 1.0000x reference)
#include <cuda_runtime.h>
#include <math.h>

#define MAX_NE 50048
#define MAX_NR 1024
#define MAX_E  800000
#define EH 256
#define RH 64
#define STRIDE 64   // max segment degree (Poisson(16): P(>64) ~ 2e-18)

// -------- scratch (device globals; no allocation allowed) --------
__device__ float  g_seh[MAX_NE];
__device__ float  g_set[MAX_NE];
__device__ float  g_sr [MAX_NR];
__device__ float  g_M;                       // max over s_r
__device__ int    g_cnth[MAX_NE];
__device__ int    g_cntt[MAX_NE];
__device__ int2   g_adjh[MAX_NE * STRIDE];   // (rel, w bits) fixed-stride slots (head)
__device__ int2   g_adjt[MAX_NE * STRIDE];   // (tail)

__device__ __forceinline__ float leaky(float x) { return fmaxf(x, 0.01f * x); }

// ---------------- K0: zero counts + node scores + rel scores, fused ----------------
__global__ void k_scores(const float* __restrict__ xe,
                         const float* __restrict__ xr,
                         const float* __restrict__ ah,
                         const float* __restrict__ at,
                         const float* __restrict__ ar,
                         int nE, int nR, int zeroBlocks, int nodeBlocks) {
    int b = blockIdx.x;
    if (b < zeroBlocks) {
        int i = b * 256 + threadIdx.x;
        if (i < nE) { g_cnth[i] = 0; g_cntt[i] = 0; }
    } else if (b < zeroBlocks + nodeBlocks) {
        // warp per node, float4 loads
        int lane = threadIdx.x & 31;
        int n = (b - zeroBlocks) * 8 + (threadIdx.x >> 5);
        if (n >= nE) return;
        const float4* row = reinterpret_cast<const float4*>(xe + (size_t)n * EH);
        const float4* a4h = reinterpret_cast<const float4*>(ah);
        const float4* a4t = reinterpret_cast<const float4*>(at);
        float sh = 0.f, st = 0.f;
#pragma unroll
        for (int j = 0; j < 2; j++) {
            float4 v = row[lane + 32 * j];
            float4 wh = a4h[lane + 32 * j];
            float4 wt = a4t[lane + 32 * j];
            sh = fmaf(v.x, wh.x, fmaf(v.y, wh.y, fmaf(v.z, wh.z, fmaf(v.w, wh.w, sh))));
            st = fmaf(v.x, wt.x, fmaf(v.y, wt.y, fmaf(v.z, wt.z, fmaf(v.w, wt.w, st))));
        }
#pragma unroll
        for (int o = 16; o; o >>= 1) {
            sh += __shfl_xor_sync(0xFFFFFFFFu, sh, o);
            st += __shfl_xor_sync(0xFFFFFFFFu, st, o);
        }
        if (lane == 0) { g_seh[n] = sh; g_set[n] = st; }
    } else {
        // warp per relation
        int lane = threadIdx.x & 31;
        int r = (b - zeroBlocks - nodeBlocks) * 8 + (threadIdx.x >> 5);
        if (r >= nR) return;
        const float* row = xr + (size_t)r * RH;
        float s = fmaf(row[lane], ar[lane], row[lane + 32] * ar[lane + 32]);
#pragma unroll
        for (int o = 16; o; o >>= 1) s += __shfl_xor_sync(0xFFFFFFFFu, s, o);
        if (lane == 0) g_sr[r] = s;
    }
}

// ---------------- K1: M = max(s_r) (1 block) ----------------
__global__ void k_max(int nR) {
    __shared__ float sm[32];
    int t = threadIdx.x;                 // 1024 threads
    float m = (t < nR) ? g_sr[t] : -3.4e38f;
#pragma unroll
    for (int o = 16; o; o >>= 1) m = fmaxf(m, __shfl_xor_sync(0xFFFFFFFFu, m, o));
    if ((t & 31) == 0) sm[t >> 5] = m;
    __syncthreads();
    if (t < 32) {
        float v = sm[t];
#pragma unroll
        for (int o = 16; o; o >>= 1) v = fmaxf(v, __shfl_xor_sync(0xFFFFFFFFu, v, o));
        if (t == 0) g_M = v;
    }
}

// ---------------- K2: edge pass, 2 edges/thread with batched independent loads ----------
__global__ void k_edges(const int* __restrict__ ei,
                        const int* __restrict__ rel, int E) {
    int e0 = (blockIdx.x * blockDim.x + threadIdx.x) * 2;
    if (e0 >= E) return;
    int e1 = e0 + 1;
    bool v1 = e1 < E;
    float M = g_M;

    // batch the coalesced index loads
    int h0 = ei[e0],      t0 = ei[E + e0],      r0 = rel[e0];
    int h1 = v1 ? ei[e1] : 0, t1 = v1 ? ei[E + e1] : 0, r1 = v1 ? rel[e1] : 0;

    // 4 independent random gathers in flight (+2 L1-resident)
    float sh0 = g_seh[h0], st0 = g_set[t0];
    float sh1 = g_seh[h1], st1 = g_set[t1];
    float sr0 = g_sr[r0],  sr1 = g_sr[r1];

    float wh0 = __expf(leaky(sh0 + sr0) - leaky(sh0 + M));
    float wt0 = __expf(leaky(st0 + sr0) - leaky(st0 + M));
    float wh1 = __expf(leaky(sh1 + sr1) - leaky(sh1 + M));
    float wt1 = __expf(leaky(st1 + sr1) - leaky(st1 + M));

    int rh0 = atomicAdd(&g_cnth[h0], 1);
    if (rh0 < STRIDE) g_adjh[h0 * STRIDE + rh0] = make_int2(r0, __float_as_int(wh0));
    int rt0 = atomicAdd(&g_cntt[t0], 1);
    if (rt0 < STRIDE) g_adjt[t0 * STRIDE + rt0] = make_int2(r0, __float_as_int(wt0));
    if (v1) {
        int rh1 = atomicAdd(&g_cnth[h1], 1);
        if (rh1 < STRIDE) g_adjh[h1 * STRIDE + rh1] = make_int2(r1, __float_as_int(wh1));
        int rt1 = atomicAdd(&g_cntt[t1], 1);
        if (rt1 < STRIDE) g_adjt[t1 * STRIDE + rt1] = make_int2(r1, __float_as_int(wt1));
    }
}

// ---------------- K3: warp per (node, branch); 8-lane groups -> 4 edges in flight ------
__global__ void k_gather(const float* __restrict__ xr,
                         float* __restrict__ out, int nE) {
    int gw = (blockIdx.x * blockDim.x + threadIdx.x) >> 5;
    int n = gw >> 1;
    if (n >= nE) return;
    bool isHead = (gw & 1) == 0;
    int lane = threadIdx.x & 31;
    int g  = lane >> 3;                  // group 0..3: edges g, g+4, g+8, ...
    int k8 = lane & 7;                   // this lane covers float4 chunks k8 and k8+8

    int deg = isHead ? g_cnth[n] : g_cntt[n];
    deg = min(deg, STRIDE);
    const int2* p = (isHead ? g_adjh : g_adjt) + n * STRIDE;

    float4 acc0 = make_float4(0.f, 0.f, 0.f, 0.f);
    float4 acc1 = make_float4(0.f, 0.f, 0.f, 0.f);
    float den = 0.f;
    const float4* xr4 = reinterpret_cast<const float4*>(xr);

#pragma unroll 2
    for (int j = g; j < deg; j += 4) {
        int2 aw = p[j];                  // uniform within each 8-lane group
        float w = __int_as_float(aw.y);
        den += w;
        const float4* row = xr4 + aw.x * (RH / 4);   // L1-resident 256KB table
        float4 m0 = row[k8];
        float4 m1 = row[k8 + 8];
        acc0.x = fmaf(w, m0.x, acc0.x);
        acc0.y = fmaf(w, m0.y, acc0.y);
        acc0.z = fmaf(w, m0.z, acc0.z);
        acc0.w = fmaf(w, m0.w, acc0.w);
        acc1.x = fmaf(w, m1.x, acc1.x);
        acc1.y = fmaf(w, m1.y, acc1.y);
        acc1.z = fmaf(w, m1.z, acc1.z);
        acc1.w = fmaf(w, m1.w, acc1.w);
    }

    // combine the 4 groups (lanes i, i^8, i^16, i^24 hold the same chunk pair)
#pragma unroll
    for (int o = 8; o <= 16; o <<= 1) {
        den    += __shfl_xor_sync(0xFFFFFFFFu, den,    o);
        acc0.x += __shfl_xor_sync(0xFFFFFFFFu, acc0.x, o);
        acc0.y += __shfl_xor_sync(0xFFFFFFFFu, acc0.y, o);
        acc0.z += __shfl_xor_sync(0xFFFFFFFFu, acc0.z, o);
        acc0.w += __shfl_xor_sync(0xFFFFFFFFu, acc0.w, o);
        acc1.x += __shfl_xor_sync(0xFFFFFFFFu, acc1.x, o);
        acc1.y += __shfl_xor_sync(0xFFFFFFFFu, acc1.y, o);
        acc1.z += __shfl_xor_sync(0xFFFFFFFFu, acc1.z, o);
        acc1.w += __shfl_xor_sync(0xFFFFFFFFu, acc1.w, o);
    }

    if (lane < 8) {
        float inv = (den > 0.f) ? 1.0f / den : 0.f;
        float4* o4 = reinterpret_cast<float4*>(out + (size_t)n * (2 * RH))
                     + (isHead ? 0 : 16);
        o4[k8]     = make_float4(acc0.x * inv, acc0.y * inv, acc0.z * inv, acc0.w * inv);
        o4[k8 + 8] = make_float4(acc1.x * inv, acc1.y * inv, acc1.z * inv, acc1.w * inv);
    }
}

// ---------------- launch ----------------
extern "C" void kernel_launch(void* const* d_in, const int* in_sizes, int n_in,
                              void* d_out, int out_size) {
    const float* xe  = (const float*)d_in[0];
    const float* xr  = (const float*)d_in[1];
    const int*   ei  = (const int*)d_in[2];   // int32 (JAX x64 disabled)
    const int*   rel = (const int*)d_in[3];
    // d_in[4], d_in[5] (line graph) unused by the reference output
    const float* ahw = (const float*)d_in[6];
    const float* atw = (const float*)d_in[7];
    const float* arw = (const float*)d_in[8];

    int nE = in_sizes[0] / EH;   // 50000
    int nR = in_sizes[1] / RH;   // 1000
    int E  = in_sizes[3];        // 800000
    if (nE > MAX_NE) nE = MAX_NE;
    if (nR > MAX_NR) nR = MAX_NR;
    if (E  > MAX_E)  E  = MAX_E;

    float* out = (float*)d_out;

    int zeroBlocks = (nE + 255) / 256;
    int nodeBlocks = (nE + 7) / 8;
    int relBlocks  = (nR + 7) / 8;
    int edgeThreads = (E + 1) / 2;
    int gatherWarps = 2 * nE;
    int gatherBlocks = (gatherWarps * 32 + 255) / 256;

    k_scores<<<zeroBlocks + nodeBlocks + relBlocks, 256>>>(
        xe, xr, ahw, atw, arw, nE, nR, zeroBlocks, nodeBlocks);
    k_max<<<1, 1024>>>(nR);
    k_edges<<<(edgeThreads + 255) / 256, 256>>>(ei, rel, E);
    k_gather<<<gatherBlocks, 256>>>(xr, out, nE);
}

// round 16
// speedup vs baseline: 1.4348x; 1.4348x over previous
#include <cuda_runtime.h>
#include <math.h>

#define MAX_NE 50048
#define MAX_NR 1024
#define MAX_E  800000
#define EH 256
#define RH 64
#define STRIDE 64   // max segment degree (Poisson(16): P(>64) ~ 2e-18)

// -------- scratch (device globals; no allocation allowed) --------
__device__ float  g_seh[MAX_NE];
__device__ float  g_set[MAX_NE];
__device__ float  g_sr [MAX_NR];
__device__ float  g_M;                       // max over s_r
__device__ int    g_cnth[MAX_NE];
__device__ int    g_cntt[MAX_NE];
__device__ int2   g_adjh[MAX_NE * STRIDE];   // (rel, w bits) fixed-stride slots (head)
__device__ int2   g_adjt[MAX_NE * STRIDE];   // (tail)

__device__ __forceinline__ float leaky(float x) { return fmaxf(x, 0.01f * x); }

// ---------------- K0: zero counts + node scores + rel scores, fused ----------------
__global__ void k_scores(const float* __restrict__ xe,
                         const float* __restrict__ xr,
                         const float* __restrict__ ah,
                         const float* __restrict__ at,
                         const float* __restrict__ ar,
                         int nE, int nR, int zeroBlocks, int nodeBlocks) {
    int b = blockIdx.x;
    if (b < zeroBlocks) {
        int i = b * 256 + threadIdx.x;
        if (i < nE) { g_cnth[i] = 0; g_cntt[i] = 0; }
    } else if (b < zeroBlocks + nodeBlocks) {
        // warp per node, float4 loads
        int lane = threadIdx.x & 31;
        int n = (b - zeroBlocks) * 8 + (threadIdx.x >> 5);
        if (n >= nE) return;
        const float4* row = reinterpret_cast<const float4*>(xe + (size_t)n * EH);
        const float4* a4h = reinterpret_cast<const float4*>(ah);
        const float4* a4t = reinterpret_cast<const float4*>(at);
        float sh = 0.f, st = 0.f;
#pragma unroll
        for (int j = 0; j < 2; j++) {
            float4 v = row[lane + 32 * j];
            float4 wh = a4h[lane + 32 * j];
            float4 wt = a4t[lane + 32 * j];
            sh = fmaf(v.x, wh.x, fmaf(v.y, wh.y, fmaf(v.z, wh.z, fmaf(v.w, wh.w, sh))));
            st = fmaf(v.x, wt.x, fmaf(v.y, wt.y, fmaf(v.z, wt.z, fmaf(v.w, wt.w, st))));
        }
#pragma unroll
        for (int o = 16; o; o >>= 1) {
            sh += __shfl_xor_sync(0xFFFFFFFFu, sh, o);
            st += __shfl_xor_sync(0xFFFFFFFFu, st, o);
        }
        if (lane == 0) { g_seh[n] = sh; g_set[n] = st; }
    } else {
        // warp per relation
        int lane = threadIdx.x & 31;
        int r = (b - zeroBlocks - nodeBlocks) * 8 + (threadIdx.x >> 5);
        if (r >= nR) return;
        const float* row = xr + (size_t)r * RH;
        float s = fmaf(row[lane], ar[lane], row[lane + 32] * ar[lane + 32]);
#pragma unroll
        for (int o = 16; o; o >>= 1) s += __shfl_xor_sync(0xFFFFFFFFu, s, o);
        if (lane == 0) g_sr[r] = s;
    }
}

// ---------------- K1: M = max(s_r) (1 block) ----------------
__global__ void k_max(int nR) {
    __shared__ float sm[32];
    int t = threadIdx.x;                 // 1024 threads
    float m = (t < nR) ? g_sr[t] : -3.4e38f;
#pragma unroll
    for (int o = 16; o; o >>= 1) m = fmaxf(m, __shfl_xor_sync(0xFFFFFFFFu, m, o));
    if ((t & 31) == 0) sm[t >> 5] = m;
    __syncthreads();
    if (t < 32) {
        float v = sm[t];
#pragma unroll
        for (int o = 16; o; o >>= 1) v = fmaxf(v, __shfl_xor_sync(0xFFFFFFFFu, v, o));
        if (t == 0) g_M = v;
    }
}

// ---------------- K2: edge pass (R14 shape): hist atomic -> rank -> weight -> slot ----
__global__ void k_edges(const int* __restrict__ ei,
                        const int* __restrict__ rel, int E) {
    int e = blockIdx.x * blockDim.x + threadIdx.x;
    if (e >= E) return;
    int h = ei[e];
    int t = ei[E + e];
    int r = rel[e];
    float M = g_M;
    float sr = g_sr[r];                  // 4KB, L1-resident
    float sh = g_seh[h], st = g_set[t];  // L2 random gathers
    // B(n) = leaky(s + M) >= leaky(s + sr) for all r (monotone); exp arg <= 0
    float wh = __expf(leaky(sh + sr) - leaky(sh + M));
    float wt = __expf(leaky(st + sr) - leaky(st + M));
    int rh = atomicAdd(&g_cnth[h], 1);
    if (rh < STRIDE) g_adjh[h * STRIDE + rh] = make_int2(r, __float_as_int(wh));
    int rt = atomicAdd(&g_cntt[t], 1);
    if (rt < STRIDE) g_adjt[t * STRIDE + rt] = make_int2(r, __float_as_int(wt));
}

// ---------------- K3: warp per (node, branch); halves process even/odd PAIRS via int4 --
__global__ void k_gather(const float* __restrict__ xr,
                         float* __restrict__ out, int nE) {
    int gw = (blockIdx.x * blockDim.x + threadIdx.x) >> 5;
    int n = gw >> 1;
    if (n >= nE) return;
    bool isHead = (gw & 1) == 0;
    int lane = threadIdx.x & 31;
    int q = lane >> 4;                   // 0: even pairs, 1: odd pairs
    int k = lane & 15;                   // float4 index within the 64-dim row

    int deg = isHead ? g_cnth[n] : g_cntt[n];
    deg = min(deg, STRIDE);
    const int2* p = (isHead ? g_adjh : g_adjt) + n * STRIDE;
    const int4* p4 = reinterpret_cast<const int4*>(p);   // 512B-aligned base

    float4 acc = make_float4(0.f, 0.f, 0.f, 0.f);
    float den = 0.f;
    const float4* xr4 = reinterpret_cast<const float4*>(xr);

    int npairs = deg >> 1;
    // half q handles pairs q, q+2, q+4, ... (each pair = one aligned LDG.128 of 2 slots)
#pragma unroll 2
    for (int i = q; i < npairs; i += 2) {
        int4 aw = p4[i];                 // (r0, w0, r1, w1) uniform within 16-lane half
        float w0 = __int_as_float(aw.y);
        float w1 = __int_as_float(aw.w);
        float4 m0 = xr4[aw.x * (RH / 4) + k];   // 2 independent L1-resident row loads
        float4 m1 = xr4[aw.z * (RH / 4) + k];
        den += w0 + w1;
        acc.x = fmaf(w0, m0.x, fmaf(w1, m1.x, acc.x));
        acc.y = fmaf(w0, m0.y, fmaf(w1, m1.y, acc.y));
        acc.z = fmaf(w0, m0.z, fmaf(w1, m1.z, acc.z));
        acc.w = fmaf(w0, m0.w, fmaf(w1, m1.w, acc.w));
    }
    // odd tail edge (only half 0 takes it)
    if ((deg & 1) && q == 0) {
        int2 aw = p[deg - 1];
        float w = __int_as_float(aw.y);
        float4 m = xr4[aw.x * (RH / 4) + k];
        den += w;
        acc.x = fmaf(w, m.x, acc.x);
        acc.y = fmaf(w, m.y, acc.y);
        acc.z = fmaf(w, m.z, acc.z);
        acc.w = fmaf(w, m.w, acc.w);
    }

    // combine the two halves (lane i <-> lane i^16 hold same k)
    den   += __shfl_xor_sync(0xFFFFFFFFu, den,   16);
    acc.x += __shfl_xor_sync(0xFFFFFFFFu, acc.x, 16);
    acc.y += __shfl_xor_sync(0xFFFFFFFFu, acc.y, 16);
    acc.z += __shfl_xor_sync(0xFFFFFFFFu, acc.z, 16);
    acc.w += __shfl_xor_sync(0xFFFFFFFFu, acc.w, 16);

    if (lane < 16) {
        float inv = (den > 0.f) ? 1.0f / den : 0.f;
        float4* o4 = reinterpret_cast<float4*>(out + (size_t)n * (2 * RH));
        // head warp writes float4 slots 0..15 (dims [0,64)), tail warp 16..31
        o4[(isHead ? 0 : 16) + k] =
            make_float4(acc.x * inv, acc.y * inv, acc.z * inv, acc.w * inv);
    }
}

// ---------------- launch ----------------
extern "C" void kernel_launch(void* const* d_in, const int* in_sizes, int n_in,
                              void* d_out, int out_size) {
    const float* xe  = (const float*)d_in[0];
    const float* xr  = (const float*)d_in[1];
    const int*   ei  = (const int*)d_in[2];   // int32 (JAX x64 disabled)
    const int*   rel = (const int*)d_in[3];
    // d_in[4], d_in[5] (line graph) unused by the reference output
    const float* ahw = (const float*)d_in[6];
    const float* atw = (const float*)d_in[7];
    const float* arw = (const float*)d_in[8];

    int nE = in_sizes[0] / EH;   // 50000
    int nR = in_sizes[1] / RH;   // 1000
    int E  = in_sizes[3];        // 800000
    if (nE > MAX_NE) nE = MAX_NE;
    if (nR > MAX_NR) nR = MAX_NR;
    if (E  > MAX_E)  E  = MAX_E;

    float* out = (float*)d_out;

    int zeroBlocks = (nE + 255) / 256;
    int nodeBlocks = (nE + 7) / 8;
    int relBlocks  = (nR + 7) / 8;
    int gatherWarps = 2 * nE;
    int gatherBlocks = (gatherWarps * 32 + 255) / 256;

    k_scores<<<zeroBlocks + nodeBlocks + relBlocks, 256>>>(
        xe, xr, ahw, atw, arw, nE, nR, zeroBlocks, nodeBlocks);
    k_max<<<1, 1024>>>(nR);
    k_edges<<<(E + 255) / 256, 256>>>(ei, rel, E);
    k_gather<<<gatherBlocks, 256>>>(xr, out, nE);
}

// round 17
// speedup vs baseline: 1.5857x; 1.1051x over previous
#include <cuda_runtime.h>
#include <math.h>

#define MAX_NE 50048
#define MAX_NR 1024
#define MAX_E  800000
#define EH 256
#define RH 64
#define STRIDE 64   // max segment degree (Poisson(16): P(>64) ~ 2e-18)

// -------- scratch (device globals; no allocation allowed) --------
__device__ float    g_seh[MAX_NE];
__device__ float    g_set[MAX_NE];
__device__ float    g_sr [MAX_NR];
__device__ unsigned g_Menc;                  // order-preserving-encoded max over s_r
__device__ int      g_cnth[MAX_NE];
__device__ int      g_cntt[MAX_NE];
__device__ int2     g_adjh[MAX_NE * STRIDE]; // (rel, w bits) fixed-stride slots (head)
__device__ int2     g_adjt[MAX_NE * STRIDE]; // (tail)

// Order-preserving float<->uint map so atomicMax(unsigned) == float max.
// 0 is below every encoded finite float (enc(-FLT_MAX) = 0x00800000).
__device__ __forceinline__ unsigned enc_f(float f) {
    unsigned u = __float_as_uint(f);
    return (u & 0x80000000u) ? ~u : (u | 0x80000000u);
}
__device__ __forceinline__ float dec_f(unsigned u) {
    u = (u & 0x80000000u) ? (u & 0x7FFFFFFFu) : ~u;
    return __uint_as_float(u);
}
__device__ __forceinline__ float leaky(float x) { return fmaxf(x, 0.01f * x); }

// ---------------- K0: zero counts + node scores + rel scores(+max), fused ----------------
__global__ void k_scores(const float* __restrict__ xe,
                         const float* __restrict__ xr,
                         const float* __restrict__ ah,
                         const float* __restrict__ at,
                         const float* __restrict__ ar,
                         int nE, int nR, int zeroBlocks, int nodeBlocks) {
    int b = blockIdx.x;
    if (b < zeroBlocks) {
        int i = b * 256 + threadIdx.x;
        if (i < nE) { g_cnth[i] = 0; g_cntt[i] = 0; }
    } else if (b < zeroBlocks + nodeBlocks) {
        // warp per node, float4 loads
        int lane = threadIdx.x & 31;
        int n = (b - zeroBlocks) * 8 + (threadIdx.x >> 5);
        if (n >= nE) return;
        const float4* row = reinterpret_cast<const float4*>(xe + (size_t)n * EH);
        const float4* a4h = reinterpret_cast<const float4*>(ah);
        const float4* a4t = reinterpret_cast<const float4*>(at);
        float sh = 0.f, st = 0.f;
#pragma unroll
        for (int j = 0; j < 2; j++) {
            float4 v = row[lane + 32 * j];
            float4 wh = a4h[lane + 32 * j];
            float4 wt = a4t[lane + 32 * j];
            sh = fmaf(v.x, wh.x, fmaf(v.y, wh.y, fmaf(v.z, wh.z, fmaf(v.w, wh.w, sh))));
            st = fmaf(v.x, wt.x, fmaf(v.y, wt.y, fmaf(v.z, wt.z, fmaf(v.w, wt.w, st))));
        }
#pragma unroll
        for (int o = 16; o; o >>= 1) {
            sh += __shfl_xor_sync(0xFFFFFFFFu, sh, o);
            st += __shfl_xor_sync(0xFFFFFFFFu, st, o);
        }
        if (lane == 0) { g_seh[n] = sh; g_set[n] = st; }
    } else {
        // warp per relation; lane 0 also feeds the global max (g_Menc memset to 0 upstream)
        int lane = threadIdx.x & 31;
        int r = (b - zeroBlocks - nodeBlocks) * 8 + (threadIdx.x >> 5);
        if (r >= nR) return;
        const float* row = xr + (size_t)r * RH;
        float s = fmaf(row[lane], ar[lane], row[lane + 32] * ar[lane + 32]);
#pragma unroll
        for (int o = 16; o; o >>= 1) s += __shfl_xor_sync(0xFFFFFFFFu, s, o);
        if (lane == 0) {
            g_sr[r] = s;
            atomicMax(&g_Menc, enc_f(s));
        }
    }
}

// ---------------- K1: edge pass (R14 shape): hist atomic -> rank -> weight -> slot ----
__global__ void k_edges(const int* __restrict__ ei,
                        const int* __restrict__ rel, int E) {
    int e = blockIdx.x * blockDim.x + threadIdx.x;
    if (e >= E) return;
    int h = ei[e];
    int t = ei[E + e];
    int r = rel[e];
    float M = dec_f(g_Menc);
    float sr = g_sr[r];                  // 4KB, L1-resident
    float sh = g_seh[h], st = g_set[t];  // L2 random gathers
    // B(n) = leaky(s + M) >= leaky(s + sr) for all r (monotone); exp arg <= 0
    float wh = __expf(leaky(sh + sr) - leaky(sh + M));
    float wt = __expf(leaky(st + sr) - leaky(st + M));
    int rh = atomicAdd(&g_cnth[h], 1);
    if (rh < STRIDE) g_adjh[h * STRIDE + rh] = make_int2(r, __float_as_int(wh));
    int rt = atomicAdd(&g_cntt[t], 1);
    if (rt < STRIDE) g_adjt[t * STRIDE + rt] = make_int2(r, __float_as_int(wt));
}

// ---------------- K2: warp per (node, branch); lane halves process even/odd edges ------
// (exact R14 measured-best shape: 39.3us, regs 32, occ 77%)
__global__ void k_gather(const float* __restrict__ xr,
                         float* __restrict__ out, int nE) {
    int gw = (blockIdx.x * blockDim.x + threadIdx.x) >> 5;
    int n = gw >> 1;
    if (n >= nE) return;
    bool isHead = (gw & 1) == 0;
    int lane = threadIdx.x & 31;
    int q = lane >> 4;                   // 0: even edges, 1: odd edges
    int k = lane & 15;                   // float4 index within the 64-dim row

    int deg = isHead ? g_cnth[n] : g_cntt[n];
    deg = min(deg, STRIDE);
    const int2* p = (isHead ? g_adjh : g_adjt) + n * STRIDE;

    float4 acc = make_float4(0.f, 0.f, 0.f, 0.f);
    float den = 0.f;
    const float4* xr4 = reinterpret_cast<const float4*>(xr);

    // half q processes edges q, q+2, q+4, ... -> serial depth ~deg/2
#pragma unroll 2
    for (int j = q; j < deg; j += 2) {
        int2 aw = p[j];                  // uniform within each 16-lane half
        float w = __int_as_float(aw.y);
        den += w;
        float4 m = xr4[aw.x * (RH / 4) + k];   // L1-resident 256KB table
        acc.x = fmaf(w, m.x, acc.x);
        acc.y = fmaf(w, m.y, acc.y);
        acc.z = fmaf(w, m.z, acc.z);
        acc.w = fmaf(w, m.w, acc.w);
    }

    // combine the two halves (lane i <-> lane i^16 hold same k)
    den   += __shfl_xor_sync(0xFFFFFFFFu, den,   16);
    acc.x += __shfl_xor_sync(0xFFFFFFFFu, acc.x, 16);
    acc.y += __shfl_xor_sync(0xFFFFFFFFu, acc.y, 16);
    acc.z += __shfl_xor_sync(0xFFFFFFFFu, acc.z, 16);
    acc.w += __shfl_xor_sync(0xFFFFFFFFu, acc.w, 16);

    if (lane < 16) {
        float inv = (den > 0.f) ? 1.0f / den : 0.f;
        float4* o4 = reinterpret_cast<float4*>(out + (size_t)n * (2 * RH));
        // head warp writes float4 slots 0..15 (dims [0,64)), tail warp 16..31
        o4[(isHead ? 0 : 16) + k] =
            make_float4(acc.x * inv, acc.y * inv, acc.z * inv, acc.w * inv);
    }
}

// ---------------- launch ----------------
extern "C" void kernel_launch(void* const* d_in, const int* in_sizes, int n_in,
                              void* d_out, int out_size) {
    const float* xe  = (const float*)d_in[0];
    const float* xr  = (const float*)d_in[1];
    const int*   ei  = (const int*)d_in[2];   // int32 (JAX x64 disabled)
    const int*   rel = (const int*)d_in[3];
    // d_in[4], d_in[5] (line graph) unused by the reference output
    const float* ahw = (const float*)d_in[6];
    const float* atw = (const float*)d_in[7];
    const float* arw = (const float*)d_in[8];

    int nE = in_sizes[0] / EH;   // 50000
    int nR = in_sizes[1] / RH;   // 1000
    int E  = in_sizes[3];        // 800000
    if (nE > MAX_NE) nE = MAX_NE;
    if (nR > MAX_NR) nR = MAX_NR;
    if (E  > MAX_E)  E  = MAX_E;

    float* out = (float*)d_out;

    // reset the encoded max (0 < enc(any float)); stream-ordered before k_scores
    void* menc_ptr = nullptr;
    cudaGetSymbolAddress(&menc_ptr, g_Menc);
    cudaMemsetAsync(menc_ptr, 0, sizeof(unsigned), 0);

    int zeroBlocks = (nE + 255) / 256;
    int nodeBlocks = (nE + 7) / 8;
    int relBlocks  = (nR + 7) / 8;
    int gatherWarps = 2 * nE;
    int gatherBlocks = (gatherWarps * 32 + 255) / 256;

    k_scores<<<zeroBlocks + nodeBlocks + relBlocks, 256>>>(
        xe, xr, ahw, atw, arw, nE, nR, zeroBlocks, nodeBlocks);
    k_edges<<<(E + 255) / 256, 256>>>(ei, rel, E);
    k_gather<<<gatherBlocks, 256>>>(xr, out, nE);
}